// round 1
// baseline (speedup 1.0000x reference)
#include <cuda_runtime.h>

// Problem constants: B=2, N=1024, T=64, H=64
#define NN 1024
#define HH 64

// Scratch (allocation-free rule: __device__ globals)
// layout [b][h][n] so kernel2 tile loads are coalesced and smem-friendly
__device__ float g_p[2 * HH * NN];
__device__ float g_q[2 * HH * NN];
__device__ float g_U[NN];
__device__ float g_V[NN];

// ---------------------------------------------------------------------------
// Kernel 1: per-node projections
//   p[b,n,h] = sum_t x[b,n,t] * W1[h,t]          (source half)
//   q[b,n,h] = sum_t x[b,n,t] * W1[h,64+t] + b1  (target half)
//   U[n] = 0.2525 * sum_{b,h} w2[h]*p[b,n,h]
//   V[n] = 0.2525 * sum_{b,h} w2[h]*q[b,n,h] + b2
// 1024 blocks (one per n), 64 threads (one per h).
// ---------------------------------------------------------------------------
__global__ void k1_proj(const float* __restrict__ x, const float* __restrict__ W1,
                        const float* __restrict__ b1, const float* __restrict__ W2,
                        const float* __restrict__ b2) {
    __shared__ float sW1t[128][65];   // transposed W1 [col][row], padded
    __shared__ float xr[2][64];
    __shared__ float redU[64];
    __shared__ float redV[64];
    const int n = blockIdx.x;
    const int h = threadIdx.x;  // 0..63

    // cooperative coalesced load of W1 (64x128), store transposed
    #pragma unroll 16
    for (int k = 0; k < 128; ++k) {
        int l = k * 64 + h;             // linear index into W1
        sW1t[l & 127][l >> 7] = W1[l];
    }
    xr[0][h] = x[n * 64 + h];
    xr[1][h] = x[(1024 + n) * 64 + h];
    __syncthreads();

    float p0 = 0.f, p1 = 0.f, q0 = 0.f, q1 = 0.f;
    #pragma unroll 8
    for (int t = 0; t < 64; ++t) {
        float wa = sW1t[t][h];
        float wb = sW1t[64 + t][h];
        float x0 = xr[0][t], x1 = xr[1][t];
        p0 = fmaf(x0, wa, p0); p1 = fmaf(x1, wa, p1);
        q0 = fmaf(x0, wb, q0); q1 = fmaf(x1, wb, q1);
    }
    float bb = b1[h];
    q0 += bb; q1 += bb;

    g_p[h * 1024 + n]        = p0;
    g_p[(64 + h) * 1024 + n] = p1;
    g_q[h * 1024 + n]        = q0;
    g_q[(64 + h) * 1024 + n] = q1;

    float w = W2[h];
    redU[h] = w * (p0 + p1);
    redV[h] = w * (q0 + q1);
    __syncthreads();
    for (int s = 32; s > 0; s >>= 1) {
        if (h < s) { redU[h] += redU[h + s]; redV[h] += redV[h + s]; }
        __syncthreads();
    }
    if (h == 0) {
        g_U[n] = 0.2525f * redU[0];
        g_V[n] = 0.2525f * redV[0] + b2[0];
    }
}

// ---------------------------------------------------------------------------
// Kernel 2: pairwise |z| accumulation + linear terms
//   out[i,j] = sum_{b,h} 0.2475*w2[h]*|p[b,i,h]+q[b,j,h]| + U[i] + V[j]
// Grid 16x16 blocks (64x64 pair tile), block 16x16 threads (4x4 register tile).
// ---------------------------------------------------------------------------
__global__ void __launch_bounds__(256) k2_pair(const float* __restrict__ W2,
                                               float* __restrict__ out) {
    __shared__ __align__(16) float ps[64][64];  // [h][i]
    __shared__ __align__(16) float qs[64][64];  // [h][j]
    __shared__ float swq[64];
    const int tx = threadIdx.x, ty = threadIdx.y;
    const int tid = ty * 16 + tx;
    const int i0 = blockIdx.y * 64, j0 = blockIdx.x * 64;

    if (tid < 64) swq[tid] = 0.2475f * W2[tid];

    float acc[4][4];
    #pragma unroll
    for (int r = 0; r < 4; ++r)
        #pragma unroll
        for (int c = 0; c < 4; ++c) acc[r][c] = 0.f;

    for (int b = 0; b < 2; ++b) {
        const float* pg = g_p + b * 64 * 1024;
        const float* qg = g_q + b * 64 * 1024;
        __syncthreads();   // also covers swq on first iter, prior reads on second
        #pragma unroll
        for (int k = 0; k < 4; ++k) {
            int l = k * 256 + tid;        // float4 index, 0..1023
            int hh = l >> 4;              // 16 float4 per 64-float row
            int io = (l & 15) << 2;
            *(float4*)&ps[hh][io] = *(const float4*)&pg[hh * 1024 + i0 + io];
            *(float4*)&qs[hh][io] = *(const float4*)&qg[hh * 1024 + j0 + io];
        }
        __syncthreads();

        #pragma unroll 8
        for (int h = 0; h < 64; ++h) {
            float4 pf = *(const float4*)&ps[h][ty << 2];
            float4 qf = *(const float4*)&qs[h][tx << 2];
            float w = swq[h];
            float pr[4] = {pf.x, pf.y, pf.z, pf.w};
            float qc[4] = {qf.x, qf.y, qf.z, qf.w};
            #pragma unroll
            for (int r = 0; r < 4; ++r)
                #pragma unroll
                for (int c = 0; c < 4; ++c)
                    acc[r][c] = fmaf(w, fabsf(pr[r] + qc[c]), acc[r][c]);
        }
    }

    float u[4], v[4];
    #pragma unroll
    for (int r = 0; r < 4; ++r) u[r] = g_U[i0 + (ty << 2) + r];
    #pragma unroll
    for (int c = 0; c < 4; ++c) v[c] = g_V[j0 + (tx << 2) + c];
    #pragma unroll
    for (int r = 0; r < 4; ++r) {
        float4 o;
        o.x = acc[r][0] + u[r] + v[0];
        o.y = acc[r][1] + u[r] + v[1];
        o.z = acc[r][2] + u[r] + v[2];
        o.w = acc[r][3] + u[r] + v[3];
        *(float4*)&out[(i0 + (ty << 2) + r) * 1024 + j0 + (tx << 2)] = o;
    }
}

// ---------------------------------------------------------------------------
// Kernel 3: per-row gumbel + argmax -> one-hot (straight-through == hard)
// 1024 blocks (one per row), 256 threads. Reads out (logits), overwrites with
// one-hot. First-index tie-break to match jnp.argmax.
// ---------------------------------------------------------------------------
__global__ void k3_argmax(const float* __restrict__ gu, float* __restrict__ out) {
    __shared__ float sv[256];
    __shared__ int si[256];
    const int i = blockIdx.x, tid = threadIdx.x;

    float best = -3.0e38f;
    int bj = 1 << 30;
    #pragma unroll
    for (int k = 0; k < 4; ++k) {
        int j = k * 256 + tid;
        float u = gu[i * 1024 + j];
        float g = -logf(-logf(u + 1e-10f) + 1e-10f);
        float v = out[i * 1024 + j] + g;
        if (v > best || (v == best && j < bj)) { best = v; bj = j; }
    }
    sv[tid] = best; si[tid] = bj;
    __syncthreads();
    for (int s = 128; s > 0; s >>= 1) {
        if (tid < s) {
            float v2 = sv[tid + s]; int j2 = si[tid + s];
            if (v2 > sv[tid] || (v2 == sv[tid] && j2 < si[tid])) {
                sv[tid] = v2; si[tid] = j2;
            }
        }
        __syncthreads();
    }
    const int arg = si[0];
    #pragma unroll
    for (int k = 0; k < 4; ++k) {
        int j = k * 256 + tid;
        out[i * 1024 + j] = (j == arg) ? 1.0f : 0.0f;
    }
}

// ---------------------------------------------------------------------------
extern "C" void kernel_launch(void* const* d_in, const int* in_sizes, int n_in,
                              void* d_out, int out_size) {
    const float* x  = (const float*)d_in[0];   // [2,1024,64]
    const float* W1 = (const float*)d_in[1];   // [64,128]
    const float* b1 = (const float*)d_in[2];   // [64]
    const float* W2 = (const float*)d_in[3];   // [1,64]
    const float* b2 = (const float*)d_in[4];   // [1]
    const float* gu = (const float*)d_in[5];   // [1024,1024]
    float* out = (float*)d_out;                // [1024,1024] fp32

    k1_proj<<<1024, 64>>>(x, W1, b1, W2, b2);
    k2_pair<<<dim3(16, 16), dim3(16, 16)>>>(W2, out);
    k3_argmax<<<1024, 256>>>(gu, out);
}